// round 9
// baseline (speedup 1.0000x reference)
#include <cuda_runtime.h>
#include <cstdint>

#define NT 1024
#define NW 32
#define TT 20
#define BIMG 64
#define NBLK 192
#define AMAX 9408

// per-block partial losses: [block][obj, cls, loc]
__device__ float g_part[NBLK * 3];
__device__ int g_done = 0;

__device__ __forceinline__ float warpSumF(float v) {
    for (int o = 16; o > 0; o >>= 1) v += __shfl_down_sync(0xffffffffu, v, o);
    return v;
}
__device__ __forceinline__ int warpSumI(int v) {
    for (int o = 16; o > 0; o >>= 1) v += __shfl_down_sync(0xffffffffu, v, o);
    return v;
}

struct RedBuf {
    float f[NW + 1][3];
    int   i[NW + 1][2];
};

// fused block reduction: 3 floats + 2 ints
__device__ __forceinline__ void blockRed5(float& a, float& b, float& c,
                                          int& d, int& e, RedBuf* r) {
    int lane = threadIdx.x & 31, wid = threadIdx.x >> 5;
    a = warpSumF(a); b = warpSumF(b); c = warpSumF(c);
    d = warpSumI(d); e = warpSumI(e);
    if (lane == 0) {
        r->f[wid][0] = a; r->f[wid][1] = b; r->f[wid][2] = c;
        r->i[wid][0] = d; r->i[wid][1] = e;
    }
    __syncthreads();
    if (threadIdx.x < 32) {
        float aa = (lane < NW) ? r->f[lane][0] : 0.f;
        float bb = (lane < NW) ? r->f[lane][1] : 0.f;
        float cc = (lane < NW) ? r->f[lane][2] : 0.f;
        int   dd = (lane < NW) ? r->i[lane][0] : 0;
        int   ee = (lane < NW) ? r->i[lane][1] : 0;
        aa = warpSumF(aa); bb = warpSumF(bb); cc = warpSumF(cc);
        dd = warpSumI(dd); ee = warpSumI(ee);
        if (lane == 0) {
            r->f[NW][0] = aa; r->f[NW][1] = bb; r->f[NW][2] = cc;
            r->i[NW][0] = dd; r->i[NW][1] = ee;
        }
    }
    __syncthreads();
    a = r->f[NW][0]; b = r->f[NW][1]; c = r->f[NW][2];
    d = r->i[NW][0]; e = r->i[NW][1];
    __syncthreads();
}

template <int F, int STRIDE>
__device__ __forceinline__ void scale_body(
    int img, int bid,
    const float* __restrict__ pred,
    const float4* s_tb, const float* s_area, const int* s_tl,
    unsigned long long* s_best, unsigned* s_mask,
    float* s_val, unsigned char* s_mt, RedBuf* red, int* s_cnt,
    float* out)
{
    constexpr int F2 = F * F;
    constexpr int A = F2 * 3;
    constexpr int TX = (F + 7) / 8;   // tiles in x (8 cols per tile)
    constexpr int TY = (F + 3) / 4;   // tiles in y (4 rows per tile)
    constexpr int NTILE = TX * TY;
    const float stride_f = (float)STRIDE;
    const float inv_s = 1.0f / stride_f;   // stride is a power of 2: exact
    const float h0 = stride_f, h1 = 1.25f * stride_f, h2 = 1.5f * stride_f;
    const float* pb = pred + (size_t)img * 24 * F2;
    const int tid = threadIdx.x, lane = tid & 31, wid = tid >> 5;
    const int dx = lane & 7, dy = lane >> 3;

    // ---- build per-tile target bitmask (conservative rasterization) ----
    if (tid < NTILE) s_mask[tid] = 0u;
    __syncthreads();
    if (tid < TT) {
        int t = tid;
        float4 tb = s_tb[t];
        // conservative tile-rect: any tile whose inflated bbox intersects the
        // target is included; extra tiles are harmless (IoU computes to 0).
        int tx0 = max(0, (int)floorf(((tb.x - h2) * inv_s - 7.5f) * 0.125f) - 1);
        int tx1 = min(TX - 1, (int)ceilf(((tb.z + h2) * inv_s - 0.5f) * 0.125f) + 1);
        int ty0 = max(0, (int)floorf(((tb.y - h2) * inv_s - 3.5f) * 0.25f) - 1);
        int ty1 = min(TY - 1, (int)ceilf(((tb.w + h2) * inv_s - 0.5f) * 0.25f) + 1);
        unsigned bit = 1u << t;
        for (int r = ty0; r <= ty1; r++)
            for (int c = tx0; c <= tx1; c++)
                atomicOr(&s_mask[r * TX + c], bit);
    }
    __syncthreads();

    // ---- phase A: warp-tiled IoU over masked targets only ----
    for (int ti = wid; ti < NTILE; ti += NW) {
        int tcol = ti % TX, trow = ti / TX;
        int col = tcol * 8 + dx, row = trow * 4 + dy;
        bool valid = (col < F) && (row < F);
        int cell = row * F + col;
        float cx = (col + 0.5f) * stride_f;
        float cy = (row + 0.5f) * stride_f;

        float biou[3] = {0.f, 0.f, 0.f};
        int bt[3] = {0, 0, 0};
        unsigned m = s_mask[ti];
        while (m) {
            int t = __ffs(m) - 1;       // ascending t: ties -> lowest t (argmax)
            m &= m - 1;
            float4 tb = s_tb[t];
            float ta = s_area[t];
            unsigned long long cand = 0ull;
#pragma unroll
            for (int k = 0; k < 3; k++) {
                float hk = (k == 0) ? h0 : ((k == 1) ? h1 : h2);
                float wx = fminf(cx + hk, tb.z) - fmaxf(cx - hk, tb.x);
                float wy = fminf(cy + hk, tb.w) - fmaxf(cy - hk, tb.y);
                wx = fmaxf(wx, 0.f);
                wy = fmaxf(wy, 0.f);
                float inter = wx * wy;
                float aarea = (2.f * hk) * (2.f * hk);  // exact (ints in fp32)
                float iou = inter / (aarea + ta - inter + 1e-9f);
                if (iou > biou[k]) { biou[k] = iou; bt[k] = t; }
                unsigned long long pk =
                    ((unsigned long long)__float_as_uint(iou) << 32) |
                    (unsigned long long)(0xFFFFFFFFu - (unsigned)(cell * 3 + k));
                if (pk > cand) cand = pk;
            }
            // zero-iou cands never exceed the guard (iou=0, anchor 0)
            if (valid) atomicMax(&s_best[t], cand);
        }
        if (valid) {
#pragma unroll
            for (int k = 0; k < 3; k++) {
                s_val[cell * 3 + k] = biou[k];
                s_mt[cell * 3 + k] = (unsigned char)bt[k];
            }
        }
    }
    __syncthreads();

    // ---- phase B: best-anchor override (sequential t: last-wins on dups) ----
    if (tid == 0) {
#pragma unroll
        for (int t = 0; t < TT; t++) {
            unsigned a = 0xFFFFFFFFu - (unsigned)(s_best[t] & 0xFFFFFFFFull);
            s_mt[a] = (unsigned char)(0x80 | t);
        }
    }
    __syncthreads();

    // ---- phase C: per-anchor losses ----
    int np = 0, nn = 0;
    float pbce = 0.f, csum = 0.f, lsum = 0.f;
    for (int cell = tid; cell < F2; cell += NT) {
        float obj[3];
        obj[0] = pb[4 * F2 + cell];
        obj[1] = pb[12 * F2 + cell];
        obj[2] = pb[20 * F2 + cell];
        int row = cell / F, col = cell - row * F;
        float cx = (col + 0.5f) * stride_f;
        float cy = (row + 0.5f) * stride_f;
#pragma unroll
        for (int k = 0; k < 3; k++) {
            int a = cell * 3 + k;
            float iou = s_val[a];
            unsigned m = s_mt[a];
            bool ov = (m & 0x80) != 0;
            int t = m & 0x7F;
            bool pos = ov || (iou >= 0.5f);
            bool neg = (!ov) && (iou < 0.3f);
            float x = obj[k];
            float bce = fmaxf(x, 0.f) - (pos ? x : 0.f) + log1pf(expf(-fabsf(x)));

            if (pos) {
                np++;
                pbce += bce;
                int cb = k * 8;
                float c0 = pb[(cb + 5) * F2 + cell];
                float c1 = pb[(cb + 6) * F2 + cell];
                float c2 = pb[(cb + 7) * F2 + cell];
                float mx = fmaxf(c0, fmaxf(c1, c2));
                float lse = mx + logf(expf(c0 - mx) + expf(c1 - mx) + expf(c2 - mx));
                int tgt = s_tl[t] - 1;
                float ct = (tgt == 0) ? c0 : ((tgt == 1) ? c1 : c2);
                csum += lse - ct;

                float hk = (k == 0) ? h0 : ((k == 1) ? h1 : h2);
                float aw = 2.f * hk, ah = 2.f * hk;
                float4 tb = s_tb[t];
                float gw = tb.z - tb.x, gh = tb.w - tb.y;
                float gcx = (tb.x + tb.z) * 0.5f, gcy = (tb.y + tb.w) * 0.5f;
                float td0 = (gcx - cx) / aw;
                float td1 = (gcy - cy) / ah;
                float td2 = logf(gw / aw);
                float td3 = logf(gh / ah);
                float d0 = pb[(cb + 0) * F2 + cell];
                float d1 = pb[(cb + 1) * F2 + cell];
                float d2 = pb[(cb + 2) * F2 + cell];
                float d3 = pb[(cb + 3) * F2 + cell];
                float e;
                e = fabsf(d0 - td0); lsum += (e < 1.f) ? 0.5f * e * e : e - 0.5f;
                e = fabsf(d1 - td1); lsum += (e < 1.f) ? 0.5f * e * e : e - 0.5f;
                e = fabsf(d2 - td2); lsum += (e < 1.f) ? 0.5f * e * e : e - 0.5f;
                e = fabsf(d3 - td3); lsum += (e < 1.f) ? 0.5f * e * e : e - 0.5f;
            }
            // neg BCE (always > 0); invalid entries -> bit pattern 0
            s_val[a] = neg ? bce : 0.0f;
            nn += neg ? 1 : 0;
        }
    }

    // zero phase-D counters (barrier provided by blockRed5 below)
    if (tid < 31) s_cnt[tid] = 0;

    int tnp = np, tnn = nn;
    float tpb = pbce, tcs = csum, tls = lsum;
    blockRed5(tpb, tcs, tls, tnp, tnn, red);

    // ---- phase D: exact top-`need` sum among negative BCEs (bitwise k-select) ----
    int need = min(3 * tnp, tnn);
    float topk = 0.f;
    if (need > 0) {
        const uint4* v4 = (const uint4*)s_val;
        unsigned u = 0;
        for (int bit = 30; bit >= 0; --bit) {
            unsigned cand = u | (1u << bit);
            int c = 0;
            for (int i = tid; i < A / 4; i += NT) {
                uint4 v = v4[i];
                c += (v.x >= cand) + (v.y >= cand) + (v.z >= cand) + (v.w >= cand);
            }
            c = warpSumI(c);
            if (lane == 0) atomicAdd(&s_cnt[bit], c);
            __syncthreads();
            if ((unsigned)s_cnt[bit] >= (unsigned)need) u = cand;
        }
        // u = bit pattern of the need-th largest; sum strictly greater + fill ties
        float sgt = 0.f;
        int cgt = 0;
        for (int i = tid; i < A / 4; i += NT) {
            uint4 v = v4[i];
            if (v.x > u) { sgt += __uint_as_float(v.x); cgt++; }
            if (v.y > u) { sgt += __uint_as_float(v.y); cgt++; }
            if (v.z > u) { sgt += __uint_as_float(v.z); cgt++; }
            if (v.w > u) { sgt += __uint_as_float(v.w); cgt++; }
        }
        int dummy1 = 0;
        float dz1 = 0.f, dz2 = 0.f;
        blockRed5(sgt, dz1, dz2, cgt, dummy1, red);
        topk = sgt + (float)(need - cgt) * __uint_as_float(u);
    }

    // ---- tail: write partials; last block finalizes ----
    if (tid == 0) {
        g_part[bid * 3 + 0] = (tpb + topk) / (float)max(tnp + need, 1);
        g_part[bid * 3 + 1] = tcs / (float)max(tnp, 1);
        g_part[bid * 3 + 2] = tls / (float)max(4 * tnp, 1);
        __threadfence();
        int ticket = atomicAdd(&g_done, 1);
        red->i[0][0] = (ticket == NBLK - 1) ? 1 : 0;
    }
    __syncthreads();
    if (red->i[0][0] && tid < 32) {
        __threadfence();
        float o = 0.f, c = 0.f, l = 0.f;
        for (int i = lane; i < NBLK; i += 32) {
            o += g_part[i * 3 + 0];
            c += g_part[i * 3 + 1];
            l += g_part[i * 3 + 2];
        }
        o = warpSumF(o); c = warpSumF(c); l = warpSumF(l);
        if (lane == 0) {
            float ob = o / (float)BIMG;
            float cl = c / (float)BIMG;
            float lc = l / (float)BIMG;
            out[0] = ob;
            out[1] = cl;
            out[2] = lc;
            out[3] = ob + cl + 2.f * lc;
            g_done = 0;  // reset for next graph replay
        }
    }
}

__global__ void __launch_bounds__(NT) det_loss_kernel(
    const float* __restrict__ pred1, const float* __restrict__ pred2,
    const float* __restrict__ pred3,
    const float* __restrict__ tboxes, const int* __restrict__ tlabels,
    float* out)
{
    const int bid = blockIdx.x;
    // heavy scale-0 blocks are bids 0..63 -> all land in wave 1 on distinct
    // SMs; wave 2 holds only tiny scale-2 blocks.
    const int scale = bid >> 6;
    const int img = bid & 63;

    __shared__ float4 s_tb[TT];
    __shared__ float s_area[TT];
    __shared__ int s_tl[TT];
    __shared__ unsigned long long s_best[TT];
    __shared__ RedBuf red;
    __shared__ int s_cnt[31];
    __shared__ unsigned s_mask[98];   // max tiles: F=56 -> 7x14

    extern __shared__ unsigned char dynsm[];
    float* s_val = (float*)dynsm;
    unsigned char* s_mt = (unsigned char*)(s_val + AMAX);

    if (threadIdx.x < TT) {
        int t = threadIdx.x;
        const float* tb = tboxes + ((size_t)img * TT + t) * 4;
        float x0 = tb[0], y0 = tb[1], x1 = tb[2], y1 = tb[3];
        s_tb[t] = make_float4(x0, y0, x1, y1);
        s_area[t] = (x1 - x0) * (y1 - y0);
        s_tl[t] = tlabels[img * TT + t];
        s_best[t] = (unsigned long long)0xFFFFFFFFu;  // guard: iou=0, anchor=0
    }
    __syncthreads();

    if (scale == 0)
        scale_body<56, 8>(img, bid, pred1, s_tb, s_area, s_tl, s_best, s_mask, s_val, s_mt, &red, s_cnt, out);
    else if (scale == 1)
        scale_body<28, 16>(img, bid, pred2, s_tb, s_area, s_tl, s_best, s_mask, s_val, s_mt, &red, s_cnt, out);
    else
        scale_body<14, 32>(img, bid, pred3, s_tb, s_area, s_tl, s_best, s_mask, s_val, s_mt, &red, s_cnt, out);
}

extern "C" void kernel_launch(void* const* d_in, const int* in_sizes, int n_in,
                              void* d_out, int out_size)
{
    const float* pred1  = (const float*)d_in[0];
    const float* pred2  = (const float*)d_in[1];
    const float* pred3  = (const float*)d_in[2];
    const float* tboxes = (const float*)d_in[6];
    const int*   tlab   = (const int*)d_in[7];
    float* out = (float*)d_out;

    const int smem = AMAX * 5;  // 47040 B dynamic + ~1.7KB static < 48KB
    det_loss_kernel<<<NBLK, NT, smem>>>(pred1, pred2, pred3, tboxes, tlab, out);
}

// round 10
// speedup vs baseline: 1.4853x; 1.4853x over previous
#include <cuda_runtime.h>
#include <cstdint>

#define NT 1024
#define NW 32
#define TT 20
#define BIMG 64
#define NBLK 192
#define AMAX 9408

// per-block partial losses: [block][obj, cls, loc]
__device__ float g_part[NBLK * 3];
__device__ int g_done = 0;

__device__ __forceinline__ float warpSumF(float v) {
    for (int o = 16; o > 0; o >>= 1) v += __shfl_down_sync(0xffffffffu, v, o);
    return v;
}
__device__ __forceinline__ int warpSumI(int v) {
    for (int o = 16; o > 0; o >>= 1) v += __shfl_down_sync(0xffffffffu, v, o);
    return v;
}

struct RedBuf {
    float f[NW + 1][3];
    int   i[NW + 1][2];
};

// fused block reduction: 3 floats + 2 ints
__device__ __forceinline__ void blockRed5(float& a, float& b, float& c,
                                          int& d, int& e, RedBuf* r) {
    int lane = threadIdx.x & 31, wid = threadIdx.x >> 5;
    a = warpSumF(a); b = warpSumF(b); c = warpSumF(c);
    d = warpSumI(d); e = warpSumI(e);
    if (lane == 0) {
        r->f[wid][0] = a; r->f[wid][1] = b; r->f[wid][2] = c;
        r->i[wid][0] = d; r->i[wid][1] = e;
    }
    __syncthreads();
    if (threadIdx.x < 32) {
        float aa = (lane < NW) ? r->f[lane][0] : 0.f;
        float bb = (lane < NW) ? r->f[lane][1] : 0.f;
        float cc = (lane < NW) ? r->f[lane][2] : 0.f;
        int   dd = (lane < NW) ? r->i[lane][0] : 0;
        int   ee = (lane < NW) ? r->i[lane][1] : 0;
        aa = warpSumF(aa); bb = warpSumF(bb); cc = warpSumF(cc);
        dd = warpSumI(dd); ee = warpSumI(ee);
        if (lane == 0) {
            r->f[NW][0] = aa; r->f[NW][1] = bb; r->f[NW][2] = cc;
            r->i[NW][0] = dd; r->i[NW][1] = ee;
        }
    }
    __syncthreads();
    a = r->f[NW][0]; b = r->f[NW][1]; c = r->f[NW][2];
    d = r->i[NW][0]; e = r->i[NW][1];
    __syncthreads();
}

template <int F, int STRIDE>
__device__ __forceinline__ void scale_body(
    int img, int bid,
    const float* __restrict__ pred,
    const float4* s_tb, const float* s_area, const int* s_tl,
    unsigned long long* s_best, unsigned* s_mask,
    float* s_val, unsigned char* s_mt, RedBuf* red, int* s_cnt,
    float* out)
{
    constexpr int F2 = F * F;
    constexpr int A = F2 * 3;
    constexpr int TX = (F + 7) / 8;   // tiles in x (8 cols per tile)
    constexpr int TY = (F + 3) / 4;   // tiles in y (4 rows per tile)
    constexpr int NTILE = TX * TY;
    const float stride_f = (float)STRIDE;
    const float inv_s = 1.0f / stride_f;   // power of 2: exact
    const float h0 = stride_f, h1 = 1.25f * stride_f, h2 = 1.5f * stride_f;
    const float* pb = pred + (size_t)img * 24 * F2;
    const int tid = threadIdx.x, lane = tid & 31, wid = tid >> 5;
    const int dx = lane & 7, dy = lane >> 3;

    // ---- build per-tile target bitmask (tight, conservative-safe) ----
    if (tid < NTILE) s_mask[tid] = 0u;
    __syncthreads();
    if (tid < TT) {
        int t = tid;
        float4 tb = s_tb[t];
        float lo_x = (tb.x - h2) * inv_s, hi_x = (tb.z + h2) * inv_s;
        float lo_y = (tb.y - h2) * inv_s, hi_y = (tb.w + h2) * inv_s;
        // tile tcol overlaps iff (tcol*8+7.5) > lo_x and (tcol*8+0.5) < hi_x;
        // floor forms include boundary (iou=0, harmless); 0.01 slack vs rounding
        int tx0 = max(0, (int)floorf((lo_x - 7.5f) * 0.125f - 0.01f));
        int tx1 = min(TX - 1, (int)floorf((hi_x - 0.5f) * 0.125f + 0.01f));
        int ty0 = max(0, (int)floorf((lo_y - 3.5f) * 0.25f - 0.01f));
        int ty1 = min(TY - 1, (int)floorf((hi_y - 0.5f) * 0.25f + 0.01f));
        unsigned bit = 1u << t;
        for (int r = ty0; r <= ty1; r++)
            for (int c = tx0; c <= tx1; c++)
                atomicOr(&s_mask[r * TX + c], bit);
    }
    __syncthreads();

    // ---- phase A: warp-tiled IoU over masked targets only ----
    for (int ti = wid; ti < NTILE; ti += NW) {
        int tcol = ti % TX, trow = ti / TX;
        int col = tcol * 8 + dx, row = trow * 4 + dy;
        bool valid = (col < F) && (row < F);
        int cell = row * F + col;
        float cx = (col + 0.5f) * stride_f;
        float cy = (row + 0.5f) * stride_f;

        float biou[3] = {0.f, 0.f, 0.f};
        int bt[3] = {0, 0, 0};
        unsigned m = s_mask[ti];
        while (m) {
            int t = __ffs(m) - 1;       // ascending t: ties -> lowest t (argmax)
            m &= m - 1;
            float4 tb = s_tb[t];
            float ta = s_area[t];
            unsigned long long cand = 0ull;
#pragma unroll
            for (int k = 0; k < 3; k++) {
                float hk = (k == 0) ? h0 : ((k == 1) ? h1 : h2);
                float wx = fminf(cx + hk, tb.z) - fmaxf(cx - hk, tb.x);
                float wy = fminf(cy + hk, tb.w) - fmaxf(cy - hk, tb.y);
                wx = fmaxf(wx, 0.f);
                wy = fmaxf(wy, 0.f);
                float inter = wx * wy;
                float aarea = (2.f * hk) * (2.f * hk);  // exact (ints in fp32)
                float iou = inter / (aarea + ta - inter + 1e-9f);
                if (iou > biou[k]) { biou[k] = iou; bt[k] = t; }
                unsigned long long pk =
                    ((unsigned long long)__float_as_uint(iou) << 32) |
                    (unsigned long long)(0xFFFFFFFFu - (unsigned)(cell * 3 + k));
                if (pk > cand) cand = pk;
            }
            // only lanes with iou > 0 can beat the guard -> skip dead atomics
            if (valid && cand > 0xFFFFFFFFull) atomicMax(&s_best[t], cand);
        }
        if (valid) {
#pragma unroll
            for (int k = 0; k < 3; k++) {
                s_val[cell * 3 + k] = biou[k];
                s_mt[cell * 3 + k] = (unsigned char)bt[k];
            }
        }
    }
    __syncthreads();

    // ---- phase B: best-anchor override (sequential t: last-wins on dups) ----
    if (tid == 0) {
#pragma unroll
        for (int t = 0; t < TT; t++) {
            unsigned a = 0xFFFFFFFFu - (unsigned)(s_best[t] & 0xFFFFFFFFull);
            s_mt[a] = (unsigned char)(0x80 | t);
        }
    }
    __syncthreads();

    // ---- phase C: per-anchor losses ----
    int np = 0, nn = 0;
    float pbce = 0.f, csum = 0.f, lsum = 0.f;
    for (int cell = tid; cell < F2; cell += NT) {
        float obj[3];
        obj[0] = pb[4 * F2 + cell];
        obj[1] = pb[12 * F2 + cell];
        obj[2] = pb[20 * F2 + cell];
        int row = cell / F, col = cell - row * F;
        float cx = (col + 0.5f) * stride_f;
        float cy = (row + 0.5f) * stride_f;
#pragma unroll
        for (int k = 0; k < 3; k++) {
            int a = cell * 3 + k;
            float iou = s_val[a];
            unsigned m = s_mt[a];
            bool ov = (m & 0x80) != 0;
            int t = m & 0x7F;
            bool pos = ov || (iou >= 0.5f);
            bool neg = (!ov) && (iou < 0.3f);
            float x = obj[k];
            float bce = fmaxf(x, 0.f) - (pos ? x : 0.f) + log1pf(expf(-fabsf(x)));

            if (pos) {
                np++;
                pbce += bce;
                int cb = k * 8;
                float c0 = pb[(cb + 5) * F2 + cell];
                float c1 = pb[(cb + 6) * F2 + cell];
                float c2 = pb[(cb + 7) * F2 + cell];
                float mx = fmaxf(c0, fmaxf(c1, c2));
                float lse = mx + logf(expf(c0 - mx) + expf(c1 - mx) + expf(c2 - mx));
                int tgt = s_tl[t] - 1;
                float ct = (tgt == 0) ? c0 : ((tgt == 1) ? c1 : c2);
                csum += lse - ct;

                float hk = (k == 0) ? h0 : ((k == 1) ? h1 : h2);
                float aw = 2.f * hk, ah = 2.f * hk;
                float4 tb = s_tb[t];
                float gw = tb.z - tb.x, gh = tb.w - tb.y;
                float gcx = (tb.x + tb.z) * 0.5f, gcy = (tb.y + tb.w) * 0.5f;
                float td0 = (gcx - cx) / aw;
                float td1 = (gcy - cy) / ah;
                float td2 = logf(gw / aw);
                float td3 = logf(gh / ah);
                float d0 = pb[(cb + 0) * F2 + cell];
                float d1 = pb[(cb + 1) * F2 + cell];
                float d2 = pb[(cb + 2) * F2 + cell];
                float d3 = pb[(cb + 3) * F2 + cell];
                float e;
                e = fabsf(d0 - td0); lsum += (e < 1.f) ? 0.5f * e * e : e - 0.5f;
                e = fabsf(d1 - td1); lsum += (e < 1.f) ? 0.5f * e * e : e - 0.5f;
                e = fabsf(d2 - td2); lsum += (e < 1.f) ? 0.5f * e * e : e - 0.5f;
                e = fabsf(d3 - td3); lsum += (e < 1.f) ? 0.5f * e * e : e - 0.5f;
            }
            // neg BCE (always > 0); invalid entries -> bit pattern 0
            s_val[a] = neg ? bce : 0.0f;
            nn += neg ? 1 : 0;
        }
    }

    int tnp = np, tnn = nn;
    float tpb = pbce, tcs = csum, tls = lsum;
    blockRed5(tpb, tcs, tls, tnp, tnn, red);

    // ---- phase D: exact top-`need` sum via 4-level radix-256 select ----
    // s_mt is dead after phase C -> reuse as 256-bin histogram (1KB of 9.4KB)
    int need = min(3 * tnp, tnn);
    float topk = 0.f;
    if (need > 0) {
        int* hist = (int*)s_mt;
        const uint4* v4 = (const uint4*)s_val;
        if (tid == 0) { s_cnt[0] = 0; s_cnt[1] = need; }
#pragma unroll
        for (int L = 0; L < 4; L++) {
            const int shift = (L == 0) ? 23 : (L == 1) ? 15 : (L == 2) ? 7 : 0;
            const int nb = (L == 3) ? 128 : 256;
            const int pshift = (L == 3) ? 7 : (shift + 8);
            if (tid < nb) hist[tid] = 0;
            __syncthreads();
            unsigned u = (unsigned)s_cnt[0];
            unsigned upref = u >> pshift;
            for (int i = tid; i < A / 4; i += NT) {
                uint4 v = v4[i];
                if (v.x && (v.x >> pshift) == upref) atomicAdd(&hist[(v.x >> shift) & (nb - 1)], 1);
                if (v.y && (v.y >> pshift) == upref) atomicAdd(&hist[(v.y >> shift) & (nb - 1)], 1);
                if (v.z && (v.z >> pshift) == upref) atomicAdd(&hist[(v.z >> shift) & (nb - 1)], 1);
                if (v.w && (v.w >> pshift) == upref) atomicAdd(&hist[(v.w >> shift) & (nb - 1)], 1);
            }
            __syncthreads();
            if (tid < 32) {
                const int bpl = nb / 32;      // bins per lane
                int base = tid * bpl;
                int ls = 0;
#pragma unroll
                for (int j = 0; j < 8; j++)
                    if (j < bpl) ls += hist[base + j];
                // suffix sum over lanes: suf(l) = sum of ls for lanes >= l
                int suf = ls;
#pragma unroll
                for (int o = 1; o < 32; o <<= 1) {
                    int x = __shfl_down_sync(0xffffffffu, suf, o);
                    if (tid + o < 32) suf += x;
                }
                int k = s_cnt[1];
                unsigned ball = __ballot_sync(0xffffffffu, suf >= k);
                int lsel = 31 - __clz(ball);  // largest lane with suf >= k
                if (tid == lsel) {
                    int acc = suf - ls;       // count in bins above this lane
                    for (int j = bpl - 1; j >= 0; j--) {
                        int h = hist[base + j];
                        acc += h;
                        if (acc >= k) {
                            s_cnt[1] = k - (acc - h);
                            s_cnt[0] = (int)(u | ((unsigned)(base + j) << shift));
                            break;
                        }
                    }
                }
            }
            __syncthreads();
        }
        unsigned u = (unsigned)s_cnt[0];
        // u = exact bits of the need-th largest; sum strictly greater + fill ties
        float sgt = 0.f;
        int cgt = 0;
        for (int i = tid; i < A / 4; i += NT) {
            uint4 v = v4[i];
            if (v.x > u) { sgt += __uint_as_float(v.x); cgt++; }
            if (v.y > u) { sgt += __uint_as_float(v.y); cgt++; }
            if (v.z > u) { sgt += __uint_as_float(v.z); cgt++; }
            if (v.w > u) { sgt += __uint_as_float(v.w); cgt++; }
        }
        int dummy1 = 0;
        float dz1 = 0.f, dz2 = 0.f;
        blockRed5(sgt, dz1, dz2, cgt, dummy1, red);
        topk = sgt + (float)(need - cgt) * __uint_as_float(u);
    }

    // ---- tail: write partials; last block finalizes ----
    if (tid == 0) {
        g_part[bid * 3 + 0] = (tpb + topk) / (float)max(tnp + need, 1);
        g_part[bid * 3 + 1] = tcs / (float)max(tnp, 1);
        g_part[bid * 3 + 2] = tls / (float)max(4 * tnp, 1);
        __threadfence();
        int ticket = atomicAdd(&g_done, 1);
        red->i[0][0] = (ticket == NBLK - 1) ? 1 : 0;
    }
    __syncthreads();
    if (red->i[0][0] && tid < 32) {
        __threadfence();
        float o = 0.f, c = 0.f, l = 0.f;
        for (int i = lane; i < NBLK; i += 32) {
            o += g_part[i * 3 + 0];
            c += g_part[i * 3 + 1];
            l += g_part[i * 3 + 2];
        }
        o = warpSumF(o); c = warpSumF(c); l = warpSumF(l);
        if (lane == 0) {
            float ob = o / (float)BIMG;
            float cl = c / (float)BIMG;
            float lc = l / (float)BIMG;
            out[0] = ob;
            out[1] = cl;
            out[2] = lc;
            out[3] = ob + cl + 2.f * lc;
            g_done = 0;  // reset for next graph replay
        }
    }
}

__global__ void __launch_bounds__(NT) det_loss_kernel(
    const float* __restrict__ pred1, const float* __restrict__ pred2,
    const float* __restrict__ pred3,
    const float* __restrict__ tboxes, const int* __restrict__ tlabels,
    float* out)
{
    const int bid = blockIdx.x;
    // heavy scale-0 blocks are bids 0..63 -> all land in wave 1 on distinct
    // SMs; wave 2 holds only tiny scale-2 blocks.
    const int scale = bid >> 6;
    const int img = bid & 63;

    __shared__ float4 s_tb[TT];
    __shared__ float s_area[TT];
    __shared__ int s_tl[TT];
    __shared__ unsigned long long s_best[TT];
    __shared__ RedBuf red;
    __shared__ int s_cnt[2];
    __shared__ unsigned s_mask[98];   // max tiles: F=56 -> 7x14

    extern __shared__ unsigned char dynsm[];
    float* s_val = (float*)dynsm;
    unsigned char* s_mt = (unsigned char*)(s_val + AMAX);

    if (threadIdx.x < TT) {
        int t = threadIdx.x;
        const float* tb = tboxes + ((size_t)img * TT + t) * 4;
        float x0 = tb[0], y0 = tb[1], x1 = tb[2], y1 = tb[3];
        s_tb[t] = make_float4(x0, y0, x1, y1);
        s_area[t] = (x1 - x0) * (y1 - y0);
        s_tl[t] = tlabels[img * TT + t];
        s_best[t] = (unsigned long long)0xFFFFFFFFu;  // guard: iou=0, anchor=0
    }
    __syncthreads();

    if (scale == 0)
        scale_body<56, 8>(img, bid, pred1, s_tb, s_area, s_tl, s_best, s_mask, s_val, s_mt, &red, s_cnt, out);
    else if (scale == 1)
        scale_body<28, 16>(img, bid, pred2, s_tb, s_area, s_tl, s_best, s_mask, s_val, s_mt, &red, s_cnt, out);
    else
        scale_body<14, 32>(img, bid, pred3, s_tb, s_area, s_tl, s_best, s_mask, s_val, s_mt, &red, s_cnt, out);
}

extern "C" void kernel_launch(void* const* d_in, const int* in_sizes, int n_in,
                              void* d_out, int out_size)
{
    const float* pred1  = (const float*)d_in[0];
    const float* pred2  = (const float*)d_in[1];
    const float* pred3  = (const float*)d_in[2];
    const float* tboxes = (const float*)d_in[6];
    const int*   tlab   = (const int*)d_in[7];
    float* out = (float*)d_out;

    const int smem = AMAX * 5;  // 47040 B dynamic + ~1.7KB static < 48KB
    det_loss_kernel<<<NBLK, NT, smem>>>(pred1, pred2, pred3, tboxes, tlab, out);
}